// round 1
// baseline (speedup 1.0000x reference)
#include <cuda_runtime.h>
#include <math.h>

// Problem constants
#define NQ     512
#define NROWS  4096
#define VPR    256
#define DIM    128
#define KSEL   32
#define MEMSZ  (NROWS*VPR)

// Output layout (flat float32 concat, reference tuple order)
#define OFF_VAL   0LL                       // [512,32,128]
#define OFF_ENT   2097152LL                 // [512,32]
#define OFF_GID   2113536LL                 // [512,32]
#define OFF_SC    2129920LL                 // [512,32]
#define OFF_MASK  2146304LL                 // [512,32]
#define OFF_NDIS  2162688LL                 // scalar
#define OFF_ATTN  2162689LL                 // [512,32]

// smem layout for score kernel
#define QS_STRIDE 129                       // scalar reads -> bank = (q + kk) % 32, conflict-free
#define KS_STRIDE 260                       // 16B-aligned rows, vector reads conflict-free
#define SMEM_BYTES ((DIM*QS_STRIDE + DIM*KS_STRIDE) * 4)

// Scratch (no allocation allowed -> device globals)
__device__ float          g_rowmax[(size_t)NQ*NROWS];   // 8 MB
__device__ unsigned char  g_rowarg[(size_t)NQ*NROWS];   // 2 MB
__device__ int            g_toprow[NQ*KSEL];
__device__ float          g_topscore[NQ*KSEL];
__device__ int            g_qdis[NQ];

// ---------------------------------------------------------------------------
// Pass 1: fused scores + per-row max/argmax.
// CTA = (row, qtile of 128). Tile: 128q x 256keys x K=128, fp32 via fma.rn.f32x2.
// ---------------------------------------------------------------------------
__global__ void __launch_bounds__(256, 1)
score_kernel(const float* __restrict__ queries, const float* __restrict__ keys)
{
    extern __shared__ float smem[];
    float* Qs = smem;                        // [128][129], natural [q][k]
    float* Ks = smem + DIM * QS_STRIDE;      // [128][260], transposed [k][n]

    const int tid = threadIdx.x;
    const int row = blockIdx.x;
    const int q0  = blockIdx.y * 128;

    // ---- load Q tile (coalesced float4 reads, scalar smem writes) ----
    {
        const float4* qg = reinterpret_cast<const float4*>(queries + (size_t)q0 * DIM);
        #pragma unroll
        for (int idx = tid; idx < 128 * 32; idx += 256) {
            int q = idx >> 5, d4 = idx & 31;
            float4 v = qg[q * 32 + d4];
            float* p = Qs + q * QS_STRIDE + 4 * d4;
            p[0] = v.x; p[1] = v.y; p[2] = v.z; p[3] = v.w;
        }
    }
    // ---- load K tile transposed (coalesced reads: 4 rows x 128B per warp step) ----
    {
        const int lane = tid & 31, w = tid >> 5;
        const float4* kg = reinterpret_cast<const float4*>(keys + (size_t)row * VPR * DIM);
        #pragma unroll
        for (int g = 0; g < 8; ++g) {
            int n = w * 32 + g * 4 + (lane >> 3);
            #pragma unroll
            for (int it = 0; it < 4; ++it) {
                int d4 = (lane & 7) + 8 * it;
                float4 v = kg[n * 32 + d4];
                Ks[(4 * d4 + 0) * KS_STRIDE + n] = v.x;
                Ks[(4 * d4 + 1) * KS_STRIDE + n] = v.y;
                Ks[(4 * d4 + 2) * KS_STRIDE + n] = v.z;
                Ks[(4 * d4 + 3) * KS_STRIDE + n] = v.w;
            }
        }
    }
    __syncthreads();

    const int tn = tid & 15;      // key group
    const int tq = tid >> 4;      // query group
    const int qb = tq * 8;

    // 8 queries x 16 keys as 8 key-pairs (packed f32x2)
    unsigned long long acc[8][8];
    #pragma unroll
    for (int i = 0; i < 8; ++i)
        #pragma unroll
        for (int p = 0; p < 8; ++p) acc[i][p] = 0ull;

    #pragma unroll 4
    for (int kk = 0; kk < DIM; ++kk) {
        unsigned long long qp[8];
        #pragma unroll
        for (int i = 0; i < 8; ++i) {
            float qv = Qs[(qb + i) * QS_STRIDE + kk];
            asm("mov.b64 %0, {%1, %1};" : "=l"(qp[i]) : "f"(qv));
        }
        const unsigned long long* krow =
            reinterpret_cast<const unsigned long long*>(Ks + kk * KS_STRIDE);
        #pragma unroll
        for (int c = 0; c < 4; ++c) {
            // keys n = 64c + 4tn .. +3 (16B-aligned, conflict-free per phase)
            ulonglong2 kp = *reinterpret_cast<const ulonglong2*>(krow + 32 * c + 2 * tn);
            #pragma unroll
            for (int i = 0; i < 8; ++i) {
                asm("fma.rn.f32x2 %0, %1, %2, %0;"
                    : "+l"(acc[i][2 * c + 0]) : "l"(qp[i]), "l"(kp.x));
                asm("fma.rn.f32x2 %0, %1, %2, %0;"
                    : "+l"(acc[i][2 * c + 1]) : "l"(qp[i]), "l"(kp.y));
            }
        }
    }
    __syncthreads();   // done reading smem; reuse Qs region for reduction

    float* pv = smem;                                  // [128][16] partial max
    int*   pn = reinterpret_cast<int*>(smem + 128*16); // [128][16] partial argmax
    #pragma unroll
    for (int i = 0; i < 8; ++i) {
        float bv = -3.4e38f; int bn = 0;
        #pragma unroll
        for (int c = 0; c < 4; ++c) {
            #pragma unroll
            for (int h = 0; h < 2; ++h) {
                float lo, hi;
                asm("mov.b64 {%0, %1}, %2;" : "=f"(lo), "=f"(hi) : "l"(acc[i][2*c+h]));
                int n = 64 * c + 4 * tn + 2 * h;   // ascending within thread
                if (lo > bv) { bv = lo; bn = n; }
                if (hi > bv) { bv = hi; bn = n + 1; }
            }
        }
        pv[(qb + i) * 16 + tn] = bv;
        pn[(qb + i) * 16 + tn] = bn;
    }
    __syncthreads();

    if (tid < 128) {
        float bv = -3.4e38f; int bn = VPR;
        #pragma unroll
        for (int t = 0; t < 16; ++t) {
            float v = pv[tid * 16 + t]; int n = pn[tid * 16 + t];
            if (v > bv || (v == bv && n < bn)) { bv = v; bn = n; }  // tie -> lowest idx (jnp.argmax)
        }
        int gq = q0 + tid;
        g_rowmax[(size_t)gq * NROWS + row] = bv;
        g_rowarg[(size_t)gq * NROWS + row] = (unsigned char)bn;
    }
}

// ---------------------------------------------------------------------------
// Pass 2: top-32 rows per query, descending (== reference top-64 then sel[0..31]).
// ---------------------------------------------------------------------------
__global__ void __launch_bounds__(256)
topk_kernel()
{
    __shared__ float sv[NROWS];
    __shared__ float rv[256];
    __shared__ int   ri[256];
    const int q = blockIdx.x, tid = threadIdx.x;

    const float* src = g_rowmax + (size_t)q * NROWS;
    for (int r = tid; r < NROWS; r += 256) sv[r] = src[r];
    __syncthreads();

    for (int it = 0; it < KSEL; ++it) {
        float bv = -3.4e38f; int bi = NROWS;
        #pragma unroll
        for (int t = 0; t < 16; ++t) {
            int r = tid * 16 + t;
            float v = sv[r];
            if (v > bv) { bv = v; bi = r; }     // ascending scan -> tie keeps lowest
        }
        rv[tid] = bv; ri[tid] = bi;
        __syncthreads();
        for (int s = 128; s > 0; s >>= 1) {
            if (tid < s) {
                float v2 = rv[tid + s]; int i2 = ri[tid + s];
                if (v2 > rv[tid] || (v2 == rv[tid] && i2 < ri[tid])) { rv[tid] = v2; ri[tid] = i2; }
            }
            __syncthreads();
        }
        if (tid == 0) {
            int r = ri[0];
            g_toprow[q * KSEL + it]   = r;
            g_topscore[q * KSEL + it] = rv[0];
            sv[r] = -3.4e38f;
        }
        __syncthreads();
    }
}

// ---------------------------------------------------------------------------
// Pass 3: gathers, mask, softmax, output writes (one block per query).
// ---------------------------------------------------------------------------
__device__ __forceinline__ void put(float* out, long long off, long long lim, float v) {
    if (off < lim) out[off] = v;
}

__global__ void __launch_bounds__(128)
finalize_kernel(const float* __restrict__ values, const int* __restrict__ mem_ids,
                const int* __restrict__ ent_ids, const int* __restrict__ text_ids,
                float* __restrict__ out, long long lim)
{
    __shared__ int sid[KSEL];
    const int q = blockIdx.x, tid = threadIdx.x;

    if (tid < KSEL) {   // exactly warp 0
        int   row = g_toprow[q * KSEL + tid];
        float sc  = g_topscore[q * KSEL + tid];
        int   arg = g_rowarg[(size_t)q * NROWS + row];
        int   id  = row * VPR + arg;
        sid[tid] = id;

        int   m  = (mem_ids[id] == text_ids[q]) ? 1 : 0;
        float ms = sc - (float)m * 1e10f;

        float mx = ms;
        #pragma unroll
        for (int o = 16; o > 0; o >>= 1) mx = fmaxf(mx, __shfl_xor_sync(0xffffffffu, mx, o));
        float e = expf(ms - mx);
        float ssum = e;
        #pragma unroll
        for (int o = 16; o > 0; o >>= 1) ssum += __shfl_xor_sync(0xffffffffu, ssum, o);
        float w = e / ssum;

        int cnt = m;
        #pragma unroll
        for (int o = 16; o > 0; o >>= 1) cnt += __shfl_xor_sync(0xffffffffu, cnt, o);
        if (tid == 0) g_qdis[q] = cnt;

        long long base = (long long)q * KSEL + tid;
        put(out, OFF_ENT  + base, lim, (float)ent_ids[id]);
        put(out, OFF_GID  + base, lim, (float)id);
        put(out, OFF_SC   + base, lim, sc);
        put(out, OFF_MASK + base, lim, (float)m);
        put(out, OFF_ATTN + base, lim, w);
    }
    __syncthreads();

    // top_values gather: 32 rows x 128 floats, coalesced
    for (int j = 0; j < KSEL; ++j) {
        int id = sid[j];
        long long o = OFF_VAL + ((long long)(q * KSEL + j)) * DIM + tid;
        if (o < lim) out[o] = values[(size_t)id * DIM + tid];
    }
}

// ---------------------------------------------------------------------------
// Pass 4: n_disallowed scalar
// ---------------------------------------------------------------------------
__global__ void __launch_bounds__(512)
ndis_kernel(float* __restrict__ out, long long lim)
{
    __shared__ int s[512];
    int t = threadIdx.x;
    s[t] = g_qdis[t];
    __syncthreads();
    for (int st = 256; st > 0; st >>= 1) {
        if (t < st) s[t] += s[t + st];
        __syncthreads();
    }
    if (t == 0 && OFF_NDIS < lim) out[OFF_NDIS] = (float)s[0];
}

// ---------------------------------------------------------------------------
extern "C" void kernel_launch(void* const* d_in, const int* in_sizes, int n_in,
                              void* d_out, int out_size)
{
    const float* queries  = (const float*)d_in[0];
    const float* keys     = (const float*)d_in[1];
    const int*   mem_ids  = (const int*)d_in[2];
    const int*   ent_ids  = (const int*)d_in[3];
    const float* values   = (const float*)d_in[4];
    const int*   text_ids = (const int*)d_in[5];
    float* out = (float*)d_out;
    long long lim = (long long)out_size;

    cudaFuncSetAttribute(score_kernel, cudaFuncAttributeMaxDynamicSharedMemorySize, SMEM_BYTES);

    dim3 g1(NROWS, NQ / 128);
    score_kernel<<<g1, 256, SMEM_BYTES>>>(queries, keys);
    topk_kernel<<<NQ, 256>>>();
    finalize_kernel<<<NQ, 128>>>(values, mem_ids, ent_ids, text_ids, out, lim);
    ndis_kernel<<<1, 512>>>(out, lim);
}

// round 2
// speedup vs baseline: 1.0003x; 1.0003x over previous
#include <cuda_runtime.h>
#include <math.h>

// Problem constants
#define NQ     512
#define NROWS  4096
#define VPR    256
#define DIM    128
#define KSEL   32
#define MEMSZ  (NROWS*VPR)

// Output layout (flat float32 concat, reference tuple order)
#define OFF_VAL   0LL                       // [512,32,128]
#define OFF_ENT   2097152LL                 // [512,32]
#define OFF_GID   2113536LL                 // [512,32]
#define OFF_SC    2129920LL                 // [512,32]
#define OFF_MASK  2146304LL                 // [512,32]
#define OFF_NDIS  2162688LL                 // scalar
#define OFF_ATTN  2162689LL                 // [512,32]

// smem layout for score kernel
#define QS_STRIDE 129                       // scalar reads -> bank = (q + kk) % 32, conflict-free
#define KS_STRIDE 260                       // 16B-aligned rows, vector reads conflict-free
#define SMEM_BYTES ((DIM*QS_STRIDE + DIM*KS_STRIDE) * 4)

// Scratch (no allocation allowed -> device globals)
__device__ float          g_rowmax[(size_t)NQ*NROWS];   // 8 MB
__device__ unsigned char  g_rowarg[(size_t)NQ*NROWS];   // 2 MB
__device__ int            g_toprow[NQ*KSEL];
__device__ float          g_topscore[NQ*KSEL];
__device__ int            g_qdis[NQ];

// ---------------------------------------------------------------------------
// Pass 1: fused scores + per-row max/argmax.
// CTA = (row, qtile of 128). Tile: 128q x 256keys x K=128, fp32 via fma.rn.f32x2.
// ---------------------------------------------------------------------------
__global__ void __launch_bounds__(256, 1)
score_kernel(const float* __restrict__ queries, const float* __restrict__ keys)
{
    extern __shared__ float smem[];
    float* Qs = smem;                        // [128][129], natural [q][k]
    float* Ks = smem + DIM * QS_STRIDE;      // [128][260], transposed [k][n]

    const int tid = threadIdx.x;
    const int row = blockIdx.x;
    const int q0  = blockIdx.y * 128;

    // ---- load Q tile (coalesced float4 reads, scalar smem writes) ----
    {
        const float4* qg = reinterpret_cast<const float4*>(queries + (size_t)q0 * DIM);
        #pragma unroll
        for (int idx = tid; idx < 128 * 32; idx += 256) {
            int q = idx >> 5, d4 = idx & 31;
            float4 v = qg[q * 32 + d4];
            float* p = Qs + q * QS_STRIDE + 4 * d4;
            p[0] = v.x; p[1] = v.y; p[2] = v.z; p[3] = v.w;
        }
    }
    // ---- load K tile transposed (coalesced reads: 4 rows x 128B per warp step) ----
    {
        const int lane = tid & 31, w = tid >> 5;
        const float4* kg = reinterpret_cast<const float4*>(keys + (size_t)row * VPR * DIM);
        #pragma unroll
        for (int g = 0; g < 8; ++g) {
            int n = w * 32 + g * 4 + (lane >> 3);
            #pragma unroll
            for (int it = 0; it < 4; ++it) {
                int d4 = (lane & 7) + 8 * it;
                float4 v = kg[n * 32 + d4];
                Ks[(4 * d4 + 0) * KS_STRIDE + n] = v.x;
                Ks[(4 * d4 + 1) * KS_STRIDE + n] = v.y;
                Ks[(4 * d4 + 2) * KS_STRIDE + n] = v.z;
                Ks[(4 * d4 + 3) * KS_STRIDE + n] = v.w;
            }
        }
    }
    __syncthreads();

    const int tn = tid & 15;      // key group
    const int tq = tid >> 4;      // query group
    const int qb = tq * 8;

    // 8 queries x 16 keys as 8 key-pairs (packed f32x2)
    unsigned long long acc[8][8];
    #pragma unroll
    for (int i = 0; i < 8; ++i)
        #pragma unroll
        for (int p = 0; p < 8; ++p) acc[i][p] = 0ull;

    #pragma unroll 4
    for (int kk = 0; kk < DIM; ++kk) {
        unsigned long long qp[8];
        #pragma unroll
        for (int i = 0; i < 8; ++i) {
            float qv = Qs[(qb + i) * QS_STRIDE + kk];
            asm("mov.b64 %0, {%1, %1};" : "=l"(qp[i]) : "f"(qv));
        }
        const unsigned long long* krow =
            reinterpret_cast<const unsigned long long*>(Ks + kk * KS_STRIDE);
        #pragma unroll
        for (int c = 0; c < 4; ++c) {
            // keys n = 64c + 4tn .. +3 (16B-aligned, conflict-free per phase)
            ulonglong2 kp = *reinterpret_cast<const ulonglong2*>(krow + 32 * c + 2 * tn);
            #pragma unroll
            for (int i = 0; i < 8; ++i) {
                asm("fma.rn.f32x2 %0, %1, %2, %0;"
                    : "+l"(acc[i][2 * c + 0]) : "l"(qp[i]), "l"(kp.x));
                asm("fma.rn.f32x2 %0, %1, %2, %0;"
                    : "+l"(acc[i][2 * c + 1]) : "l"(qp[i]), "l"(kp.y));
            }
        }
    }
    __syncthreads();   // done reading smem; reuse Qs region for reduction

    float* pv = smem;                                  // [128][16] partial max
    int*   pn = reinterpret_cast<int*>(smem + 128*16); // [128][16] partial argmax
    #pragma unroll
    for (int i = 0; i < 8; ++i) {
        float bv = -3.4e38f; int bn = 0;
        #pragma unroll
        for (int c = 0; c < 4; ++c) {
            #pragma unroll
            for (int h = 0; h < 2; ++h) {
                float lo, hi;
                asm("mov.b64 {%0, %1}, %2;" : "=f"(lo), "=f"(hi) : "l"(acc[i][2*c+h]));
                int n = 64 * c + 4 * tn + 2 * h;   // ascending within thread
                if (lo > bv) { bv = lo; bn = n; }
                if (hi > bv) { bv = hi; bn = n + 1; }
            }
        }
        pv[(qb + i) * 16 + tn] = bv;
        pn[(qb + i) * 16 + tn] = bn;
    }
    __syncthreads();

    if (tid < 128) {
        float bv = -3.4e38f; int bn = VPR;
        #pragma unroll
        for (int t = 0; t < 16; ++t) {
            float v = pv[tid * 16 + t]; int n = pn[tid * 16 + t];
            if (v > bv || (v == bv && n < bn)) { bv = v; bn = n; }  // tie -> lowest idx (jnp.argmax)
        }
        int gq = q0 + tid;
        g_rowmax[(size_t)gq * NROWS + row] = bv;
        g_rowarg[(size_t)gq * NROWS + row] = (unsigned char)bn;
    }
}

// ---------------------------------------------------------------------------
// Pass 2: top-32 rows per query, descending (== reference top-64 then sel[0..31]).
// ---------------------------------------------------------------------------
__global__ void __launch_bounds__(256)
topk_kernel()
{
    __shared__ float sv[NROWS];
    __shared__ float rv[256];
    __shared__ int   ri[256];
    const int q = blockIdx.x, tid = threadIdx.x;

    const float* src = g_rowmax + (size_t)q * NROWS;
    for (int r = tid; r < NROWS; r += 256) sv[r] = src[r];
    __syncthreads();

    for (int it = 0; it < KSEL; ++it) {
        float bv = -3.4e38f; int bi = NROWS;
        #pragma unroll
        for (int t = 0; t < 16; ++t) {
            int r = tid * 16 + t;
            float v = sv[r];
            if (v > bv) { bv = v; bi = r; }     // ascending scan -> tie keeps lowest
        }
        rv[tid] = bv; ri[tid] = bi;
        __syncthreads();
        for (int s = 128; s > 0; s >>= 1) {
            if (tid < s) {
                float v2 = rv[tid + s]; int i2 = ri[tid + s];
                if (v2 > rv[tid] || (v2 == rv[tid] && i2 < ri[tid])) { rv[tid] = v2; ri[tid] = i2; }
            }
            __syncthreads();
        }
        if (tid == 0) {
            int r = ri[0];
            g_toprow[q * KSEL + it]   = r;
            g_topscore[q * KSEL + it] = rv[0];
            sv[r] = -3.4e38f;
        }
        __syncthreads();
    }
}

// ---------------------------------------------------------------------------
// Pass 3: gathers, mask, softmax, output writes (one block per query).
// ---------------------------------------------------------------------------
__device__ __forceinline__ void put(float* out, long long off, long long lim, float v) {
    if (off < lim) out[off] = v;
}

__global__ void __launch_bounds__(128)
finalize_kernel(const float* __restrict__ values, const int* __restrict__ mem_ids,
                const int* __restrict__ ent_ids, const int* __restrict__ text_ids,
                float* __restrict__ out, long long lim)
{
    __shared__ int sid[KSEL];
    const int q = blockIdx.x, tid = threadIdx.x;

    if (tid < KSEL) {   // exactly warp 0
        int   row = g_toprow[q * KSEL + tid];
        float sc  = g_topscore[q * KSEL + tid];
        int   arg = g_rowarg[(size_t)q * NROWS + row];
        int   id  = row * VPR + arg;
        sid[tid] = id;

        int   m  = (mem_ids[id] == text_ids[q]) ? 1 : 0;
        float ms = sc - (float)m * 1e10f;

        float mx = ms;
        #pragma unroll
        for (int o = 16; o > 0; o >>= 1) mx = fmaxf(mx, __shfl_xor_sync(0xffffffffu, mx, o));
        float e = expf(ms - mx);
        float ssum = e;
        #pragma unroll
        for (int o = 16; o > 0; o >>= 1) ssum += __shfl_xor_sync(0xffffffffu, ssum, o);
        float w = e / ssum;

        int cnt = m;
        #pragma unroll
        for (int o = 16; o > 0; o >>= 1) cnt += __shfl_xor_sync(0xffffffffu, cnt, o);
        if (tid == 0) g_qdis[q] = cnt;

        long long base = (long long)q * KSEL + tid;
        put(out, OFF_ENT  + base, lim, (float)ent_ids[id]);
        put(out, OFF_GID  + base, lim, (float)id);
        put(out, OFF_SC   + base, lim, sc);
        put(out, OFF_MASK + base, lim, (float)m);
        put(out, OFF_ATTN + base, lim, w);
    }
    __syncthreads();

    // top_values gather: 32 rows x 128 floats, coalesced
    for (int j = 0; j < KSEL; ++j) {
        int id = sid[j];
        long long o = OFF_VAL + ((long long)(q * KSEL + j)) * DIM + tid;
        if (o < lim) out[o] = values[(size_t)id * DIM + tid];
    }
}

// ---------------------------------------------------------------------------
// Pass 4: n_disallowed scalar
// ---------------------------------------------------------------------------
__global__ void __launch_bounds__(512)
ndis_kernel(float* __restrict__ out, long long lim)
{
    __shared__ int s[512];
    int t = threadIdx.x;
    s[t] = g_qdis[t];
    __syncthreads();
    for (int st = 256; st > 0; st >>= 1) {
        if (t < st) s[t] += s[t + st];
        __syncthreads();
    }
    if (t == 0 && OFF_NDIS < lim) out[OFF_NDIS] = (float)s[0];
}

// ---------------------------------------------------------------------------
extern "C" void kernel_launch(void* const* d_in, const int* in_sizes, int n_in,
                              void* d_out, int out_size)
{
    const float* queries  = (const float*)d_in[0];
    const float* keys     = (const float*)d_in[1];
    const int*   mem_ids  = (const int*)d_in[2];
    const int*   ent_ids  = (const int*)d_in[3];
    const float* values   = (const float*)d_in[4];
    const int*   text_ids = (const int*)d_in[5];
    float* out = (float*)d_out;
    long long lim = (long long)out_size;

    cudaFuncSetAttribute(score_kernel, cudaFuncAttributeMaxDynamicSharedMemorySize, SMEM_BYTES);

    dim3 g1(NROWS, NQ / 128);
    score_kernel<<<g1, 256, SMEM_BYTES>>>(queries, keys);
    topk_kernel<<<NQ, 256>>>();
    finalize_kernel<<<NQ, 128>>>(values, mem_ids, ent_ids, text_ids, out, lim);
    ndis_kernel<<<1, 512>>>(out, lim);
}